// round 12
// baseline (speedup 1.0000x reference)
#include <cuda_runtime.h>
#include <cuda_bf16.h>
#include <cstdint>

// Fixed shapes
#define BB 4
#define CC 256
#define PP 1024
#define NK 8192
#define AA 64
#define PL (PP * NK)
#define PVSPLIT 4

// -------- device scratch --------
__device__ unsigned g_q[BB * PP * AA / 2];            // [b][p][a/2] bf16x2
__device__ unsigned g_k[BB * NK * AA / 2];            // [b][k][a/2]
__device__ unsigned g_vt[BB * CC * NK / 2];           // [b][c][k/2]  (V^T)
// P in mma-A-fragment order: [b][q16 (64)][k16 (512)][lane (32)][reg (4)]
__device__ unsigned g_P[(size_t)BB * PL / 2];
__device__ float g_peq[PP * AA];
__device__ float g_pek[PP * AA];
__device__ float g_part[PVSPLIT * BB * PP * CC];      // fp32 partials

// -------- helpers --------
__device__ __forceinline__ uint32_t f2tf(float f) {
    uint32_t r;
    asm("cvt.rna.tf32.f32 %0, %1;" : "=r"(r) : "f"(f));
    return r;
}
__device__ __forceinline__ unsigned pack_bf16(float lo, float hi) {
    unsigned r;
    asm("cvt.rn.bf16x2.f32 %0, %1, %2;" : "=r"(r) : "f"(hi), "f"(lo));
    return r;
}
__device__ __forceinline__ void mma8(float* c, const uint32_t* a, const uint32_t* b) {
    asm volatile("mma.sync.aligned.m16n8k8.row.col.f32.tf32.tf32.f32 "
                 "{%0,%1,%2,%3}, {%4,%5,%6,%7}, {%8,%9}, {%0,%1,%2,%3};"
                 : "+f"(c[0]), "+f"(c[1]), "+f"(c[2]), "+f"(c[3])
                 : "r"(a[0]), "r"(a[1]), "r"(a[2]), "r"(a[3]), "r"(b[0]), "r"(b[1]));
}
__device__ __forceinline__ void mma16(float* c, const unsigned* a, const unsigned* b) {
    asm volatile("mma.sync.aligned.m16n8k16.row.col.f32.bf16.bf16.f32 "
                 "{%0,%1,%2,%3}, {%4,%5,%6,%7}, {%8,%9}, {%0,%1,%2,%3};"
                 : "+f"(c[0]), "+f"(c[1]), "+f"(c[2]), "+f"(c[3])
                 : "r"(a[0]), "r"(a[1]), "r"(a[2]), "r"(a[3]), "r"(b[0]), "r"(b[1]));
}
__device__ __forceinline__ void ldm_x4(unsigned* r, uint32_t addr) {
    asm volatile("ldmatrix.sync.aligned.m8n8.x4.shared.b16 {%0,%1,%2,%3}, [%4];"
                 : "=r"(r[0]), "=r"(r[1]), "=r"(r[2]), "=r"(r[3]) : "r"(addr));
}
__device__ __forceinline__ uint4 cvt4(float4 v) {
    uint4 r;
    r.x = f2tf(v.x); r.y = f2tf(v.y); r.z = f2tf(v.z); r.w = f2tf(v.w);
    return r;
}
__device__ __forceinline__ void cp_async16(uint32_t dst, const void* src) {
    asm volatile("cp.async.cg.shared.global [%0], [%1], 16;" :: "r"(dst), "l"(src));
}
#define CP_COMMIT() asm volatile("cp.async.commit_group;")
template<int N> __device__ __forceinline__ void cp_wait() {
    asm volatile("cp.async.wait_group %0;" :: "n"(N));
}
__device__ __forceinline__ uint32_t smem_u32(const void* p) {
    return (uint32_t)__cvta_generic_to_shared(p);
}

// Lane-offset builders for ldmatrix (row stride 36 uints).
__device__ __forceinline__ int laneA_off(int L) {
    return ((((L >> 3) & 1) * 8 + (L & 7)) * 36 + (L >> 4) * 4) * 4;
}
__device__ __forceinline__ int laneB_off(int L) {
    return (((L >> 4) * 8 + (L & 7)) * 36 + ((L >> 3) & 1) * 4) * 4;
}

// ============================================================================
// Kernel 1: positional-encoding projections pe_q / pe_k  [1024, 64] (fp32)
// ============================================================================
__global__ void pe_proj_kernel(const float* __restrict__ Wpx, const float* __restrict__ bpx,
                               const float* __restrict__ Wpy, const float* __restrict__ bpy) {
    int p = blockIdx.x;
    int y = p >> 5, x = p & 31;
    const float* W = blockIdx.y ? Wpy : Wpx;
    const float* bb = blockIdx.y ? bpy : bpx;
    float* outp = blockIdx.y ? g_pek : g_peq;

    __shared__ float pe[CC];
    int c = threadIdx.x;
    {
        int pos = (c < 128) ? y : x;
        int idx = (c < 128) ? c : (c - 128);
        int j = idx >> 1;
        float ang = (float)pos * expf(-logf(10000.0f) * (float)j / 64.0f);
        pe[c] = (idx & 1) ? cosf(ang) : sinf(ang);
    }
    __syncthreads();
    if (c < AA) {
        float s = 0.0f;
        #pragma unroll 8
        for (int i = 0; i < CC; i++) s += pe[i] * W[c * CC + i];
        outp[p * AA + c] = s + bb[c];
    }
}

// ============================================================================
// proj body: tf32 GEMM -> bf16 outputs, register-pipelined loads (dyn smem).
// ============================================================================
__device__ __forceinline__ void proj_body(uint32_t* sm_, int m0, int n0, int z,
                                          const float* __restrict__ A,
                                          const float* __restrict__ W,
                                          const float* __restrict__ bias,
                                          int N, int mode) {
    uint32_t (*As)[136] = (uint32_t(*)[136])sm_;
    uint32_t (*Ws)[36]  = (uint32_t(*)[36])(sm_ + 32 * 136);

    A += (size_t)z * CC * PP;

    int tid = threadIdx.x;
    int wid = tid >> 5;
    int g = (tid >> 2) & 7, tg = tid & 3;
    int mbase = (wid >> 1) * 32;
    int nbase = (wid & 1) * 32;

    float acc[2][4][4];
    #pragma unroll
    for (int i = 0; i < 2; i++)
        #pragma unroll
        for (int j = 0; j < 4; j++)
            #pragma unroll
            for (int r = 0; r < 4; r++) acc[i][j][r] = 0.0f;

    float4 ar[4], wr[2];
    auto ldA = [&](int c0) {
        #pragma unroll
        for (int i = 0; i < 4; i++) {
            int idx = i * 256 + tid;
            int row = idx >> 5, c4 = idx & 31;
            ar[i] = *(const float4*)&A[(size_t)(c0 + row) * PP + m0 + c4 * 4];
        }
    };
    auto ldW = [&](int c0) {
        #pragma unroll
        for (int i = 0; i < 2; i++) {
            int idx = i * 256 + tid;
            int row = idx >> 3, c4 = idx & 7;
            wr[i] = *(const float4*)&W[(size_t)(n0 + row) * CC + c0 + c4 * 4];
        }
    };

    ldA(0); ldW(0);

    for (int c0 = 0; c0 < CC; c0 += 32) {
        #pragma unroll
        for (int i = 0; i < 4; i++) {
            int idx = i * 256 + tid;
            int row = idx >> 5, c4 = idx & 31;
            *(uint4*)&As[row][c4 * 4] = cvt4(ar[i]);
        }
        #pragma unroll
        for (int i = 0; i < 2; i++) {
            int idx = i * 256 + tid;
            int row = idx >> 3, c4 = idx & 7;
            *(uint4*)&Ws[row][c4 * 4] = cvt4(wr[i]);
        }
        __syncthreads();

        if (c0 + 32 < CC) { ldA(c0 + 32); ldW(c0 + 32); }

        #pragma unroll
        for (int ks = 0; ks < 4; ks++) {
            int k0 = ks * 8;
            uint32_t af[2][4], bf[4][2];
            #pragma unroll
            for (int mt = 0; mt < 2; mt++) {
                int mr = mbase + mt * 16;
                af[mt][0] = As[k0 + tg][mr + g];
                af[mt][1] = As[k0 + tg][mr + g + 8];
                af[mt][2] = As[k0 + tg + 4][mr + g];
                af[mt][3] = As[k0 + tg + 4][mr + g + 8];
            }
            #pragma unroll
            for (int nt = 0; nt < 4; nt++) {
                int nr = nbase + nt * 8;
                bf[nt][0] = Ws[nr + g][k0 + tg];
                bf[nt][1] = Ws[nr + g][k0 + tg + 4];
            }
            #pragma unroll
            for (int mt = 0; mt < 2; mt++)
                #pragma unroll
                for (int nt = 0; nt < 4; nt++)
                    mma8(acc[mt][nt], af[mt], bf[nt]);
        }
        __syncthreads();
    }

    if (mode < 2) {
        const float* extra = (mode == 0) ? g_peq : g_pek;
        unsigned* C = (mode == 0 ? g_q : g_k) + (size_t)z * PP * (N / 2);
        #pragma unroll
        for (int mt = 0; mt < 2; mt++) {
            int r0 = m0 + mbase + mt * 16 + g;
            #pragma unroll
            for (int nt = 0; nt < 4; nt++) {
                int col = n0 + nbase + nt * 8 + 2 * tg;
                float b0 = bias[col], b1 = bias[col + 1];
                float e00 = extra[r0 * AA + col],       e01 = extra[r0 * AA + col + 1];
                float e10 = extra[(r0 + 8) * AA + col], e11 = extra[(r0 + 8) * AA + col + 1];
                C[r0 * (N / 2) + col / 2] =
                    pack_bf16(acc[mt][nt][0] + b0 + e00, acc[mt][nt][1] + b1 + e01);
                C[(r0 + 8) * (N / 2) + col / 2] =
                    pack_bf16(acc[mt][nt][2] + b0 + e10, acc[mt][nt][3] + b1 + e11);
            }
        }
    } else {
        __nv_bfloat16* Cs = (__nv_bfloat16*)sm_;   // 64 x 132 bf16 rows (66 uints)
        #pragma unroll
        for (int mt = 0; mt < 2; mt++) {
            int r0 = mbase + mt * 16 + g;
            #pragma unroll
            for (int nt = 0; nt < 4; nt++) {
                int col = nbase + nt * 8 + 2 * tg;
                float b0 = bias[n0 + col], b1 = bias[n0 + col + 1];
                Cs[(col)     * 132 + r0]     = __float2bfloat16(acc[mt][nt][0] + b0);
                Cs[(col + 1) * 132 + r0]     = __float2bfloat16(acc[mt][nt][1] + b1);
                Cs[(col)     * 132 + r0 + 8] = __float2bfloat16(acc[mt][nt][2] + b0);
                Cs[(col + 1) * 132 + r0 + 8] = __float2bfloat16(acc[mt][nt][3] + b1);
            }
        }
        __syncthreads();
        int b = z >> 3, page = z & 7;
        const unsigned* Csu = (const unsigned*)Cs;
        int tid2 = threadIdx.x;
        #pragma unroll
        for (int j = 0; j < 16; j++) {
            int f = j * 256 + tid2;
            int n = f >> 6, u = f & 63;
            g_vt[(size_t)(b * CC + n0 + n) * (NK / 2) + page * 512 + m0 / 2 + u] =
                Csu[n * 66 + u];
        }
    }
}

// ============================================================================
// qk2 body: k-strip persistent QK^T + batch softmax -> fragment-ordered P.
// Block: 64q x 512k (8 tiles), Q resident, K double-buffered.
// smem: Q [9216 uints] + K[2][9216 uints] = 110592 B.
// ============================================================================
#define QK2_SMEM_BYTES (3 * 9216 * 4)

__device__ __forceinline__ void qk2_body(uint32_t* sm_, int qtile, int kstrip) {
    const uint32_t sb = smem_u32(sm_);
    const int tid = threadIdx.x;
    const int wid = tid >> 5;
    const int L = tid & 31;
    const int qbase = qtile * 64;

    // Q fill (rows = b*64 + r, 8 uint4 per row)
    #pragma unroll
    for (int j = 0; j < 8; j++) {
        int f = j * 256 + tid;
        int row = f >> 3, a4 = f & 7;
        int b = row >> 6, r = row & 63;
        cp_async16(sb + (row * 36 + a4 * 4) * 4,
                   &g_q[((b << 10) + qbase + r) * 32 + a4 * 4]);
    }
    auto pk = [&](int kt, int buf) {
        #pragma unroll
        for (int j = 0; j < 8; j++) {
            int f = j * 256 + tid;
            int row = f >> 3, a4 = f & 7;
            int b = row >> 6, r = row & 63;
            cp_async16(sb + ((1 + buf) * 9216 + row * 36 + a4 * 4) * 4,
                       &g_k[((b << 13) + kstrip * 512 + kt * 64 + r) * 32 + a4 * 4]);
        }
        CP_COMMIT();
    };
    pk(0, 0);   // group 0 = Q + K0
    pk(1, 1);   // group 1 = K1

    const int wm = wid >> 2, wn = wid & 3;
    const int qrow0 = wm * 32, kcol0 = wn * 16;
    const int aoff = laneA_off(L);
    const int boff = laneB_off(L);
    const uint32_t qa_base = sb + qrow0 * 36 * 4 + aoff;

    for (int kt = 0; kt < 8; kt++) {
        int buf = kt & 1;
        if (kt < 7) cp_wait<1>(); else cp_wait<0>();
        __syncthreads();

        const uint32_t kb_base = sb + (1 + buf) * 9216 * 4 + kcol0 * 36 * 4 + boff;

        float acc[4][2][2][4];
        #pragma unroll
        for (int b = 0; b < 4; b++)
            #pragma unroll
            for (int i = 0; i < 2; i++)
                #pragma unroll
                for (int j = 0; j < 2; j++)
                    #pragma unroll
                    for (int r = 0; r < 4; r++) acc[b][i][j][r] = 0.0f;

        #pragma unroll
        for (int ks = 0; ks < 4; ks++) {
            int k0b = ks * 32;
            #pragma unroll
            for (int b = 0; b < 4; b++) {
                unsigned af[2][4], bf[4];
                ldm_x4(af[0], qa_base + b * 9216 + k0b);
                ldm_x4(af[1], qa_base + b * 9216 + 16 * 36 * 4 + k0b);
                ldm_x4(bf,    kb_base + b * 9216 + k0b);
                #pragma unroll
                for (int mt = 0; mt < 2; mt++)
                    #pragma unroll
                    for (int nt = 0; nt < 2; nt++)
                        mma16(acc[b][mt][nt], af[mt], bf + nt * 2);
            }
        }
        __syncthreads();                   // K[buf] free for refill
        if (kt + 2 < 8) pk(kt + 2, buf);

        // epilogue: register-local batch softmax -> fragment-ordered P (STG.128)
        #pragma unroll
        for (int mt = 0; mt < 2; mt++) {
            int q16 = qtile * 4 + wm * 2 + mt;
            int k16 = (kstrip * 8 + kt) * 4 + wn;
            unsigned u[4][4];
            #pragma unroll
            for (int nt = 0; nt < 2; nt++) {
                #pragma unroll
                for (int h = 0; h < 2; h++) {
                    float pa[4], pb[4];
                    #pragma unroll
                    for (int rr = 0; rr < 2; rr++) {
                        int r = 2 * h + rr;
                        float s0 = acc[0][mt][nt][r] * 0.125f;
                        float s1 = acc[1][mt][nt][r] * 0.125f;
                        float s2 = acc[2][mt][nt][r] * 0.125f;
                        float s3 = acc[3][mt][nt][r] * 0.125f;
                        float m = fmaxf(fmaxf(s0, s1), fmaxf(s2, s3));
                        float e0 = __expf(s0 - m), e1 = __expf(s1 - m);
                        float e2 = __expf(s2 - m), e3 = __expf(s3 - m);
                        float rv = 1.0f / (e0 + e1 + e2 + e3);
                        float* dst = rr ? pb : pa;
                        dst[0] = e0 * rv; dst[1] = e1 * rv;
                        dst[2] = e2 * rv; dst[3] = e3 * rv;
                    }
                    #pragma unroll
                    for (int b = 0; b < 4; b++)
                        u[b][nt * 2 + h] = pack_bf16(pa[b], pb[b]);
                }
            }
            #pragma unroll
            for (int b = 0; b < 4; b++) {
                size_t idx = (((size_t)(b * 64 + q16) * 512 + k16) * 32 + L) * 4;
                *(uint4*)&g_P[idx] = make_uint4(u[b][0], u[b][1], u[b][2], u[b][3]);
            }
        }
    }
}

// ============================================================================
// Kernel 2: merged proj_q + proj_k (288 blocks)
// ============================================================================
__global__ __launch_bounds__(256, 2) void projqk_kernel(
    const float* __restrict__ zx, const float* __restrict__ Wq, const float* __restrict__ bq,
    const float* __restrict__ zy, const float* __restrict__ Wk, const float* __restrict__ bk) {
    extern __shared__ uint32_t sm[];
    int id = blockIdx.x;
    if (id < 32) {
        proj_body(sm, (id & 7) * 128, 0, id >> 3, zx, Wq, bq, 64, 0);
    } else {
        int id2 = id - 32;
        proj_body(sm, (id2 & 7) * 128, 0, id2 >> 3, zy, Wk, bk, 64, 1);
    }
}

// ============================================================================
// Kernel 3: merged proj_v (1024) + qk2 (256) = 1280 blocks, 1 qk per 5
// ============================================================================
__global__ __launch_bounds__(256, 2) void projv_qk_kernel(
    const float* __restrict__ zy, const float* __restrict__ Wv, const float* __restrict__ bv) {
    extern __shared__ uint32_t sm[];
    int idx = blockIdx.x;
    if (idx % 5 == 0) {
        int id = idx / 5;                       // 0..255
        qk2_body(sm, id & 15, id >> 4);
    } else {
        int vid = idx - idx / 5 - 1;            // 0..1023
        proj_body(sm, (vid & 7) * 128, ((vid >> 3) & 3) * 64, vid >> 5, zy, Wv, bv, 256, 2);
    }
}

// ============================================================================
// Kernel 4: O = P @ V. A (P) loaded as fragments via LDG.128 (reg double-buf),
// V via 3-stage cp.async smem. split-K=4, BK=64. grid (8, 2, 16).
// ============================================================================
#define VS_STAGE 4608    // uints per V stage (128 rows x 36)
#define PV_SMEM_BYTES (3 * VS_STAGE * 4)   // 55296 B

__global__ __launch_bounds__(256, 2) void pv_mma() {
    extern __shared__ uint32_t sm[];
    const uint32_t sb = smem_u32(sm);

    int b = blockIdx.z >> 2;
    int split = blockIdx.z & 3;
    int m0x = blockIdx.x;                 // q-block (128 rows)
    int n0 = blockIdx.y * 128;
    int tid = threadIdx.x;
    int wid = tid >> 5;
    const int L = tid & 31;
    int g = (tid >> 2) & 7, tg = tid & 3;
    int mbase = (wid >> 1) * 32;
    int nbase = (wid & 1) * 64;

    const unsigned* Vu = g_vt + (size_t)b * CC * (NK / 2);
    const int NIT = 32;
    const int k16start = split * 128;     // k16 units

    // fragment base pointers for this warp's two m16 tiles
    const unsigned* Pab[2];
    #pragma unroll
    for (int mt = 0; mt < 2; mt++) {
        int q16 = m0x * 8 + (wid >> 1) * 2 + mt;
        Pab[mt] = g_P + ((size_t)(b * 64 + q16) * 512) * 128 + L * 4;
    }
    auto ldaf = [&](int it, int ks, int mt) -> uint4 {
        int k16 = k16start + it * 4 + ks;
        return *(const uint4*)(Pab[mt] + (size_t)k16 * 128);
    };

    auto prefetchV = [&](int it, int stage) {
        int kbu = split * 1024 + it * 32;
        #pragma unroll
        for (int j = 0; j < 4; j++) {
            int f = j * 256 + tid;
            int row = f >> 3, c4 = f & 7;
            cp_async16(sb + (stage * VS_STAGE + row * 36 + c4 * 4) * 4,
                       Vu + (size_t)(n0 + row) * (NK / 2) + kbu + c4 * 4);
        }
        CP_COMMIT();
    };

    float acc[2][8][4];
    #pragma unroll
    for (int i = 0; i < 2; i++)
        #pragma unroll
        for (int j = 0; j < 8; j++)
            #pragma unroll
            for (int r = 0; r < 4; r++) acc[i][j][r] = 0.0f;

    const int boff = laneB_off(L);
    const uint32_t vb_base = sb + nbase * 36 * 4 + boff;

    prefetchV(0, 0);
    prefetchV(1, 1);

    uint4 afc[2], afn[2];
    afc[0] = ldaf(0, 0, 0);
    afc[1] = ldaf(0, 0, 1);

    int stage = 0;
    for (int it = 0; it < NIT; it++) {
        if (it + 1 < NIT) cp_wait<1>(); else cp_wait<0>();
        __syncthreads();
        if (it + 2 < NIT) {
            int ns = stage + 2; if (ns >= 3) ns -= 3;
            prefetchV(it + 2, ns);
        }

        uint32_t stg = (uint32_t)(stage * VS_STAGE * 4);
        #pragma unroll
        for (int ks = 0; ks < 4; ks++) {
            // prefetch next A fragments (clamped at the very end; extra load is benign)
            int nit = it, nks = ks + 1;
            if (nks == 4) { nks = 0; nit = (it + 1 < NIT) ? it + 1 : it; }
            afn[0] = ldaf(nit, nks, 0);
            afn[1] = ldaf(nit, nks, 1);

            int k0b = ks * 32;
            unsigned bf[4][4];
            #pragma unroll
            for (int j = 0; j < 4; j++)
                ldm_x4(bf[j], vb_base + stg + j * 16 * 36 * 4 + k0b);
            #pragma unroll
            for (int mt = 0; mt < 2; mt++) {
                const unsigned* a = (const unsigned*)&afc[mt];
                #pragma unroll
                for (int nt = 0; nt < 8; nt++)
                    mma16(acc[mt][nt], a, bf[nt >> 1] + (nt & 1) * 2);
            }
            afc[0] = afn[0];
            afc[1] = afn[1];
        }
        if (++stage == 3) stage = 0;
    }

    float* part = g_part + (size_t)split * (BB * PP * CC);
    #pragma unroll
    for (int mt = 0; mt < 2; mt++) {
        int r0 = m0x * 128 + mbase + mt * 16 + g;
        #pragma unroll
        for (int nt = 0; nt < 8; nt++) {
            int col = n0 + nbase + nt * 8 + 2 * tg;
            __stcs((float2*)&part[(size_t)((b << 10) + r0) * CC + col],
                   make_float2(acc[mt][nt][0], acc[mt][nt][1]));
            __stcs((float2*)&part[(size_t)((b << 10) + r0 + 8) * CC + col],
                   make_float2(acc[mt][nt][2], acc[mt][nt][3]));
        }
    }
}

// ============================================================================
// Kernel 5: deterministic 4-way split-K reduction into d_out ([b][p][c])
// ============================================================================
__global__ void reduce4(float* __restrict__ out) {
    int i = blockIdx.x * blockDim.x + threadIdx.x;
    const float4* p = (const float4*)g_part;
    const int plane = BB * PP * CC / 4;
    float4 s = __ldcs(p + i);
    #pragma unroll
    for (int sp = 1; sp < PVSPLIT; sp++) {
        float4 t = __ldcs(p + (size_t)sp * plane + i);
        s.x += t.x; s.y += t.y; s.z += t.z; s.w += t.w;
    }
    ((float4*)out)[i] = s;
}

// ============================================================================
extern "C" void kernel_launch(void* const* d_in, const int* in_sizes, int n_in,
                              void* d_out, int out_size) {
    const float* zx  = (const float*)d_in[0];
    const float* zy  = (const float*)d_in[1];
    const float* Wq  = (const float*)d_in[2];
    const float* bq  = (const float*)d_in[3];
    const float* Wpx = (const float*)d_in[4];
    const float* bpx = (const float*)d_in[5];
    const float* Wk  = (const float*)d_in[6];
    const float* bk  = (const float*)d_in[7];
    const float* Wpy = (const float*)d_in[8];
    const float* bpy = (const float*)d_in[9];
    const float* Wv  = (const float*)d_in[10];
    const float* bv  = (const float*)d_in[11];
    float* out = (float*)d_out;

    const int proj_smem = 32 * 136 * 4 + 64 * 36 * 4;   // 26624 B
    cudaFuncSetAttribute(projqk_kernel, cudaFuncAttributeMaxDynamicSharedMemorySize,
                         proj_smem);
    cudaFuncSetAttribute(projv_qk_kernel, cudaFuncAttributeMaxDynamicSharedMemorySize,
                         QK2_SMEM_BYTES);
    cudaFuncSetAttribute(pv_mma, cudaFuncAttributeMaxDynamicSharedMemorySize,
                         PV_SMEM_BYTES);

    pe_proj_kernel<<<dim3(PP, 2), CC>>>(Wpx, bpx, Wpy, bpy);
    projqk_kernel<<<288, 256, proj_smem>>>(zx, Wq, bq, zy, Wk, bk);
    projv_qk_kernel<<<1280, 256, QK2_SMEM_BYTES>>>(zy, Wv, bv);
    pv_mma<<<dim3(8, 2, 16), 256, PV_SMEM_BYTES>>>();
    reduce4<<<(BB * PP * CC / 4) / 256, 256>>>(out);
}

// round 13
// speedup vs baseline: 1.1797x; 1.1797x over previous
#include <cuda_runtime.h>
#include <cuda_bf16.h>
#include <cstdint>

// Fixed shapes
#define BB 4
#define CC 256
#define PP 1024
#define NK 8192
#define AA 64
#define PL (PP * NK)
#define PVSPLIT 4

// -------- device scratch --------
__device__ unsigned g_q[BB * PP * AA / 2];            // [b][p][a/2] bf16x2
__device__ unsigned g_k[BB * NK * AA / 2];            // [b][k][a/2]
__device__ unsigned g_vt[BB * CC * NK / 2];           // [b][c][k/2]  (V^T)
__device__ unsigned g_P[(size_t)BB * PL / 2];         // [b][p][k/2]
__device__ float g_peq[PP * AA];
__device__ float g_pek[PP * AA];
__device__ float g_part[PVSPLIT * BB * PP * CC];      // fp32 partials

// -------- helpers --------
__device__ __forceinline__ uint32_t f2tf(float f) {
    uint32_t r;
    asm("cvt.rna.tf32.f32 %0, %1;" : "=r"(r) : "f"(f));
    return r;
}
__device__ __forceinline__ unsigned pack_bf16(float lo, float hi) {
    unsigned r;
    asm("cvt.rn.bf16x2.f32 %0, %1, %2;" : "=r"(r) : "f"(hi), "f"(lo));
    return r;
}
__device__ __forceinline__ void mma8(float* c, const uint32_t* a, const uint32_t* b) {
    asm volatile("mma.sync.aligned.m16n8k8.row.col.f32.tf32.tf32.f32 "
                 "{%0,%1,%2,%3}, {%4,%5,%6,%7}, {%8,%9}, {%0,%1,%2,%3};"
                 : "+f"(c[0]), "+f"(c[1]), "+f"(c[2]), "+f"(c[3])
                 : "r"(a[0]), "r"(a[1]), "r"(a[2]), "r"(a[3]), "r"(b[0]), "r"(b[1]));
}
__device__ __forceinline__ void mma16(float* c, const unsigned* a, const unsigned* b) {
    asm volatile("mma.sync.aligned.m16n8k16.row.col.f32.bf16.bf16.f32 "
                 "{%0,%1,%2,%3}, {%4,%5,%6,%7}, {%8,%9}, {%0,%1,%2,%3};"
                 : "+f"(c[0]), "+f"(c[1]), "+f"(c[2]), "+f"(c[3])
                 : "r"(a[0]), "r"(a[1]), "r"(a[2]), "r"(a[3]), "r"(b[0]), "r"(b[1]));
}
__device__ __forceinline__ void ldm_x4(unsigned* r, uint32_t addr) {
    asm volatile("ldmatrix.sync.aligned.m8n8.x4.shared.b16 {%0,%1,%2,%3}, [%4];"
                 : "=r"(r[0]), "=r"(r[1]), "=r"(r[2]), "=r"(r[3]) : "r"(addr));
}
__device__ __forceinline__ uint4 cvt4(float4 v) {
    uint4 r;
    r.x = f2tf(v.x); r.y = f2tf(v.y); r.z = f2tf(v.z); r.w = f2tf(v.w);
    return r;
}
__device__ __forceinline__ void cp_async16(uint32_t dst, const void* src) {
    asm volatile("cp.async.cg.shared.global [%0], [%1], 16;" :: "r"(dst), "l"(src));
}
#define CP_COMMIT() asm volatile("cp.async.commit_group;")
template<int N> __device__ __forceinline__ void cp_wait() {
    asm volatile("cp.async.wait_group %0;" :: "n"(N));
}
__device__ __forceinline__ uint32_t smem_u32(const void* p) {
    return (uint32_t)__cvta_generic_to_shared(p);
}

// Lane-offset builders for ldmatrix (row stride 36 uints).
__device__ __forceinline__ int laneA_off(int L) {
    return ((((L >> 3) & 1) * 8 + (L & 7)) * 36 + (L >> 4) * 4) * 4;
}
__device__ __forceinline__ int laneB_off(int L) {
    return (((L >> 4) * 8 + (L & 7)) * 36 + ((L >> 3) & 1) * 4) * 4;
}

// ============================================================================
// Kernel 1a/1b: positional-encoding projection (one side per launch)
// ============================================================================
__global__ void pe_proj_kernel(const float* __restrict__ W, const float* __restrict__ bb,
                               int which) {
    int p = blockIdx.x;
    int y = p >> 5, x = p & 31;
    float* outp = which ? g_pek : g_peq;

    __shared__ float pe[CC];
    int c = threadIdx.x;
    {
        int pos = (c < 128) ? y : x;
        int idx = (c < 128) ? c : (c - 128);
        int j = idx >> 1;
        float ang = (float)pos * expf(-logf(10000.0f) * (float)j / 64.0f);
        pe[c] = (idx & 1) ? cosf(ang) : sinf(ang);
    }
    __syncthreads();
    if (c < AA) {
        float s = 0.0f;
        #pragma unroll 8
        for (int i = 0; i < CC; i++) s += pe[i] * W[c * CC + i];
        outp[p * AA + c] = s + bb[c];
    }
}

// ============================================================================
// proj body: tf32 GEMM -> bf16 outputs, register-pipelined (streaming A loads)
// ============================================================================
__device__ __forceinline__ void proj_body(uint32_t* sm_, int m0, int n0, int z,
                                          const float* __restrict__ A,
                                          const float* __restrict__ W,
                                          const float* __restrict__ bias,
                                          int N, int mode) {
    uint32_t (*As)[136] = (uint32_t(*)[136])sm_;
    uint32_t (*Ws)[36]  = (uint32_t(*)[36])(sm_ + 32 * 136);

    A += (size_t)z * CC * PP;

    int tid = threadIdx.x;
    int wid = tid >> 5;
    int g = (tid >> 2) & 7, tg = tid & 3;
    int mbase = (wid >> 1) * 32;
    int nbase = (wid & 1) * 32;

    float acc[2][4][4];
    #pragma unroll
    for (int i = 0; i < 2; i++)
        #pragma unroll
        for (int j = 0; j < 4; j++)
            #pragma unroll
            for (int r = 0; r < 4; r++) acc[i][j][r] = 0.0f;

    float4 ar[4], wr[2];
    auto ldA = [&](int c0) {
        #pragma unroll
        for (int i = 0; i < 4; i++) {
            int idx = i * 256 + tid;
            int row = idx >> 5, c4 = idx & 31;
            ar[i] = __ldcs((const float4*)&A[(size_t)(c0 + row) * PP + m0 + c4 * 4]);
        }
    };
    auto ldW = [&](int c0) {
        #pragma unroll
        for (int i = 0; i < 2; i++) {
            int idx = i * 256 + tid;
            int row = idx >> 3, c4 = idx & 7;
            wr[i] = *(const float4*)&W[(size_t)(n0 + row) * CC + c0 + c4 * 4];
        }
    };

    ldA(0); ldW(0);

    for (int c0 = 0; c0 < CC; c0 += 32) {
        #pragma unroll
        for (int i = 0; i < 4; i++) {
            int idx = i * 256 + tid;
            int row = idx >> 5, c4 = idx & 31;
            *(uint4*)&As[row][c4 * 4] = cvt4(ar[i]);
        }
        #pragma unroll
        for (int i = 0; i < 2; i++) {
            int idx = i * 256 + tid;
            int row = idx >> 3, c4 = idx & 7;
            *(uint4*)&Ws[row][c4 * 4] = cvt4(wr[i]);
        }
        __syncthreads();

        if (c0 + 32 < CC) { ldA(c0 + 32); ldW(c0 + 32); }

        #pragma unroll
        for (int ks = 0; ks < 4; ks++) {
            int k0 = ks * 8;
            uint32_t af[2][4], bf[4][2];
            #pragma unroll
            for (int mt = 0; mt < 2; mt++) {
                int mr = mbase + mt * 16;
                af[mt][0] = As[k0 + tg][mr + g];
                af[mt][1] = As[k0 + tg][mr + g + 8];
                af[mt][2] = As[k0 + tg + 4][mr + g];
                af[mt][3] = As[k0 + tg + 4][mr + g + 8];
            }
            #pragma unroll
            for (int nt = 0; nt < 4; nt++) {
                int nr = nbase + nt * 8;
                bf[nt][0] = Ws[nr + g][k0 + tg];
                bf[nt][1] = Ws[nr + g][k0 + tg + 4];
            }
            #pragma unroll
            for (int mt = 0; mt < 2; mt++)
                #pragma unroll
                for (int nt = 0; nt < 4; nt++)
                    mma8(acc[mt][nt], af[mt], bf[nt]);
        }
        __syncthreads();
    }

    if (mode < 2) {
        const float* extra = (mode == 0) ? g_peq : g_pek;
        unsigned* C = (mode == 0 ? g_q : g_k) + (size_t)z * PP * (N / 2);
        #pragma unroll
        for (int mt = 0; mt < 2; mt++) {
            int r0 = m0 + mbase + mt * 16 + g;
            #pragma unroll
            for (int nt = 0; nt < 4; nt++) {
                int col = n0 + nbase + nt * 8 + 2 * tg;
                float b0 = bias[col], b1 = bias[col + 1];
                float e00 = extra[r0 * AA + col],       e01 = extra[r0 * AA + col + 1];
                float e10 = extra[(r0 + 8) * AA + col], e11 = extra[(r0 + 8) * AA + col + 1];
                C[r0 * (N / 2) + col / 2] =
                    pack_bf16(acc[mt][nt][0] + b0 + e00, acc[mt][nt][1] + b1 + e01);
                C[(r0 + 8) * (N / 2) + col / 2] =
                    pack_bf16(acc[mt][nt][2] + b0 + e10, acc[mt][nt][3] + b1 + e11);
            }
        }
    } else {
        __nv_bfloat16* Cs = (__nv_bfloat16*)sm_;   // 64 x 132 bf16 rows (66 uints)
        #pragma unroll
        for (int mt = 0; mt < 2; mt++) {
            int r0 = mbase + mt * 16 + g;
            #pragma unroll
            for (int nt = 0; nt < 4; nt++) {
                int col = nbase + nt * 8 + 2 * tg;
                float b0 = bias[n0 + col], b1 = bias[n0 + col + 1];
                Cs[(col)     * 132 + r0]     = __float2bfloat16(acc[mt][nt][0] + b0);
                Cs[(col + 1) * 132 + r0]     = __float2bfloat16(acc[mt][nt][1] + b1);
                Cs[(col)     * 132 + r0 + 8] = __float2bfloat16(acc[mt][nt][2] + b0);
                Cs[(col + 1) * 132 + r0 + 8] = __float2bfloat16(acc[mt][nt][3] + b1);
            }
        }
        __syncthreads();
        int b = z >> 3, page = z & 7;
        const unsigned* Csu = (const unsigned*)Cs;
        int tid2 = threadIdx.x;
        #pragma unroll
        for (int j = 0; j < 16; j++) {
            int f = j * 256 + tid2;
            int n = f >> 6, u = f & 63;
            g_vt[(size_t)(b * CC + n0 + n) * (NK / 2) + page * 512 + m0 / 2 + u] =
                Csu[n * 66 + u];
        }
    }
}

// ============================================================================
// qk body: QK^T (bf16, ldmatrix) + register-local batch softmax -> P (bf16),
// smem-staged coalesced streaming P writes.
// ============================================================================
#define QK_TILE (4 * 64 * 36)
#define QK_SMEM_BYTES (2 * QK_TILE * 4)   // 73728 B

__device__ __forceinline__ void qk_body(uint32_t* sm_, int qtile, int ktile) {
    const uint32_t sb = smem_u32(sm_);

    const int tid = threadIdx.x;
    const int wid = tid >> 5;
    const int L = tid & 31;
    const int g = (tid >> 2) & 7, tg = tid & 3;
    const int qbase = qtile * 64, kbase = ktile * 64;

    #pragma unroll
    for (int j = 0; j < 8; j++) {
        int f = j * 256 + tid;
        int row = f >> 3, a4 = f & 7;
        int b = row >> 6, r = row & 63;
        cp_async16(sb + (row * 36 + a4 * 4) * 4,
                   &g_q[((b << 10) + qbase + r) * 32 + a4 * 4]);
        cp_async16(sb + (QK_TILE + row * 36 + a4 * 4) * 4,
                   &g_k[((b << 13) + kbase + r) * 32 + a4 * 4]);
    }
    CP_COMMIT();
    cp_wait<0>();
    __syncthreads();

    const int wm = wid >> 2, wn = wid & 3;
    const int qrow0 = wm * 32, kcol0 = wn * 16;

    const int aoff = laneA_off(L);
    const int boff = laneB_off(L);
    const uint32_t qa_base = sb + qrow0 * 36 * 4 + aoff;
    const uint32_t kb_base = sb + QK_TILE * 4 + kcol0 * 36 * 4 + boff;

    float acc[4][2][2][4];
    #pragma unroll
    for (int b = 0; b < 4; b++)
        #pragma unroll
        for (int i = 0; i < 2; i++)
            #pragma unroll
            for (int j = 0; j < 2; j++)
                #pragma unroll
                for (int r = 0; r < 4; r++) acc[b][i][j][r] = 0.0f;

    #pragma unroll
    for (int ks = 0; ks < 4; ks++) {
        int k0b = ks * 32;
        #pragma unroll
        for (int b = 0; b < 4; b++) {
            unsigned af[2][4], bf[4];
            ldm_x4(af[0], qa_base + b * 9216 + k0b);
            ldm_x4(af[1], qa_base + b * 9216 + 16 * 36 * 4 + k0b);
            ldm_x4(bf,    kb_base + b * 9216 + k0b);
            #pragma unroll
            for (int mt = 0; mt < 2; mt++)
                #pragma unroll
                for (int nt = 0; nt < 2; nt++)
                    mma16(acc[b][mt][nt], af[mt], bf + nt * 2);
        }
    }

    __syncthreads();
    uint32_t* Ps = sm_;

    #pragma unroll
    for (int mt = 0; mt < 2; mt++) {
        int lo = qrow0 + mt * 16 + g;
        #pragma unroll
        for (int nt = 0; nt < 2; nt++) {
            int cu = kcol0 / 2 + nt * 4 + tg;
            float p[4][4];
            #pragma unroll
            for (int r = 0; r < 4; r++) {
                float s0 = acc[0][mt][nt][r] * 0.125f;
                float s1 = acc[1][mt][nt][r] * 0.125f;
                float s2 = acc[2][mt][nt][r] * 0.125f;
                float s3 = acc[3][mt][nt][r] * 0.125f;
                float m = fmaxf(fmaxf(s0, s1), fmaxf(s2, s3));
                float e0 = __expf(s0 - m), e1 = __expf(s1 - m);
                float e2 = __expf(s2 - m), e3 = __expf(s3 - m);
                float rv = 1.0f / (e0 + e1 + e2 + e3);
                p[r][0] = e0 * rv; p[r][1] = e1 * rv;
                p[r][2] = e2 * rv; p[r][3] = e3 * rv;
            }
            #pragma unroll
            for (int b = 0; b < 4; b++) {
                Ps[b * 2304 + lo * 36 + cu]       = pack_bf16(p[0][b], p[1][b]);
                Ps[b * 2304 + (lo + 8) * 36 + cu] = pack_bf16(p[2][b], p[3][b]);
            }
        }
    }
    __syncthreads();

    #pragma unroll
    for (int j = 0; j < 8; j++) {
        int f = j * 256 + tid;
        int b = f >> 9, r = (f >> 3) & 63, q4 = f & 7;
        uint4 val = *(const uint4*)&Ps[b * 2304 + r * 36 + q4 * 4];
        __stcs((uint4*)&g_P[(size_t)b * (PL / 2) + (size_t)(qbase + r) * (NK / 2)
                            + kbase / 2 + q4 * 4], val);
    }
}

// ============================================================================
// Kernel 2: merged proj_q + proj_k (288 blocks)
// ============================================================================
__global__ __launch_bounds__(256, 2) void projqk_kernel(
    const float* __restrict__ zx, const float* __restrict__ Wq, const float* __restrict__ bq,
    const float* __restrict__ zy, const float* __restrict__ Wk, const float* __restrict__ bk) {
    extern __shared__ uint32_t sm[];
    int id = blockIdx.x;
    if (id < 32) {
        proj_body(sm, (id & 7) * 128, 0, id >> 3, zx, Wq, bq, 64, 0);
    } else {
        int id2 = id - 32;
        proj_body(sm, (id2 & 7) * 128, 0, id2 >> 3, zy, Wk, bk, 64, 1);
    }
}

// ============================================================================
// Kernel 3: merged proj_v (1024) + qk (2048) = 3072 blocks, 1:2 interleave
// ============================================================================
__global__ __launch_bounds__(256, 2) void projv_qk_kernel(
    const float* __restrict__ zy, const float* __restrict__ Wv, const float* __restrict__ bv) {
    extern __shared__ uint32_t sm[];
    int idx = blockIdx.x;
    if (idx % 3 == 0) {
        int vid = idx / 3;
        proj_body(sm, (vid & 7) * 128, ((vid >> 3) & 3) * 64, vid >> 5, zy, Wv, bv, 256, 2);
    } else {
        int qkid = idx - idx / 3 - 1;
        qk_body(sm, qkid & 15, qkid >> 4);
    }
}

// ============================================================================
// Kernel 4: O = P @ V (bf16, ldmatrix), split-K=4, BK=64, 3-stage pipeline.
// ============================================================================
#define PS_BUF (128 * 36)
#define VS_BUF (128 * 36)
#define STAGE  (PS_BUF + VS_BUF)
#define PV_SMEM_BYTES (3 * STAGE * 4)   // 110592 B

__global__ __launch_bounds__(256, 2) void pv_mma() {
    extern __shared__ uint32_t sm[];
    const uint32_t sb = smem_u32(sm);

    int b = blockIdx.z >> 2;
    int split = blockIdx.z & 3;
    int m0 = blockIdx.x * 128, n0 = blockIdx.y * 128;
    int tid = threadIdx.x;
    int wid = tid >> 5;
    const int L = tid & 31;
    int g = (tid >> 2) & 7, tg = tid & 3;
    int mbase = (wid >> 1) * 32;
    int nbase = (wid & 1) * 64;

    const unsigned* Pu = g_P  + (size_t)b * (PL / 2);
    const unsigned* Vu = g_vt + (size_t)b * CC * (NK / 2);

    const int kstart = split * (NK / PVSPLIT);
    const int NIT = (NK / PVSPLIT) / 64;   // 32

    auto prefetch = [&](int it, int stage) {
        int kbu = (kstart + it * 64) / 2;
        #pragma unroll
        for (int j = 0; j < 4; j++) {
            int f = j * 256 + tid;
            int row = f >> 3, c4 = f & 7;
            uint32_t dst = sb + (stage * STAGE + row * 36 + c4 * 4) * 4;
            cp_async16(dst, Pu + (size_t)(m0 + row) * (NK / 2) + kbu + c4 * 4);
            uint32_t dst2 = sb + (stage * STAGE + PS_BUF + row * 36 + c4 * 4) * 4;
            cp_async16(dst2, Vu + (size_t)(n0 + row) * (NK / 2) + kbu + c4 * 4);
        }
        CP_COMMIT();
    };

    float acc[2][8][4];
    #pragma unroll
    for (int i = 0; i < 2; i++)
        #pragma unroll
        for (int j = 0; j < 8; j++)
            #pragma unroll
            for (int r = 0; r < 4; r++) acc[i][j][r] = 0.0f;

    const int aoff = laneA_off(L);
    const int boff = laneB_off(L);
    const uint32_t pa_base = sb + mbase * 36 * 4 + aoff;
    const uint32_t vb_base = sb + PS_BUF * 4 + nbase * 36 * 4 + boff;

    prefetch(0, 0);
    prefetch(1, 1);

    int stage = 0;
    for (int it = 0; it < NIT; it++) {
        if (it + 1 < NIT) cp_wait<1>(); else cp_wait<0>();
        __syncthreads();
        if (it + 2 < NIT) {
            int ns = stage + 2; if (ns >= 3) ns -= 3;
            prefetch(it + 2, ns);
        }

        uint32_t stg = (uint32_t)(stage * STAGE * 4);
        #pragma unroll
        for (int ks = 0; ks < 4; ks++) {
            int k0b = ks * 32;
            unsigned af[2][4], bf[4][4];
            ldm_x4(af[0], pa_base + stg + k0b);
            ldm_x4(af[1], pa_base + stg + 16 * 36 * 4 + k0b);
            #pragma unroll
            for (int j = 0; j < 4; j++)
                ldm_x4(bf[j], vb_base + stg + j * 16 * 36 * 4 + k0b);
            #pragma unroll
            for (int mt = 0; mt < 2; mt++)
                #pragma unroll
                for (int nt = 0; nt < 8; nt++)
                    mma16(acc[mt][nt], af[mt], bf[nt >> 1] + (nt & 1) * 2);
        }
        if (++stage == 3) stage = 0;
    }

    float* part = g_part + (size_t)split * (BB * PP * CC);
    #pragma unroll
    for (int mt = 0; mt < 2; mt++) {
        int r0 = m0 + mbase + mt * 16 + g;
        #pragma unroll
        for (int nt = 0; nt < 8; nt++) {
            int col = n0 + nbase + nt * 8 + 2 * tg;
            __stcs((float2*)&part[(size_t)((b << 10) + r0) * CC + col],
                   make_float2(acc[mt][nt][0], acc[mt][nt][1]));
            __stcs((float2*)&part[(size_t)((b << 10) + r0 + 8) * CC + col],
                   make_float2(acc[mt][nt][2], acc[mt][nt][3]));
        }
    }
}

// ============================================================================
// Kernel 5: deterministic 4-way split-K reduction into d_out ([b][p][c])
// ============================================================================
__global__ void reduce4(float* __restrict__ out) {
    int i = blockIdx.x * blockDim.x + threadIdx.x;
    const float4* p = (const float4*)g_part;
    const int plane = BB * PP * CC / 4;
    float4 s = __ldcs(p + i);
    #pragma unroll
    for (int sp = 1; sp < PVSPLIT; sp++) {
        float4 t = __ldcs(p + (size_t)sp * plane + i);
        s.x += t.x; s.y += t.y; s.z += t.z; s.w += t.w;
    }
    ((float4*)out)[i] = s;
}

// ============================================================================
extern "C" void kernel_launch(void* const* d_in, const int* in_sizes, int n_in,
                              void* d_out, int out_size) {
    const float* zx  = (const float*)d_in[0];
    const float* zy  = (const float*)d_in[1];
    const float* Wq  = (const float*)d_in[2];
    const float* bq  = (const float*)d_in[3];
    const float* Wpx = (const float*)d_in[4];
    const float* bpx = (const float*)d_in[5];
    const float* Wk  = (const float*)d_in[6];
    const float* bk  = (const float*)d_in[7];
    const float* Wpy = (const float*)d_in[8];
    const float* bpy = (const float*)d_in[9];
    const float* Wv  = (const float*)d_in[10];
    const float* bv  = (const float*)d_in[11];
    float* out = (float*)d_out;

    const int proj_smem = 32 * 136 * 4 + 64 * 36 * 4;   // 26624 B
    cudaFuncSetAttribute(projqk_kernel, cudaFuncAttributeMaxDynamicSharedMemorySize,
                         proj_smem);
    cudaFuncSetAttribute(projv_qk_kernel, cudaFuncAttributeMaxDynamicSharedMemorySize,
                         QK_SMEM_BYTES);
    cudaFuncSetAttribute(pv_mma, cudaFuncAttributeMaxDynamicSharedMemorySize,
                         PV_SMEM_BYTES);

    pe_proj_kernel<<<PP, CC>>>(Wpx, bpx, 0);                        // launch 1
    pe_proj_kernel<<<PP, CC>>>(Wpy, bpy, 1);                        // launch 2
    projqk_kernel<<<288, 256, proj_smem>>>(zx, Wq, bq, zy, Wk, bk); // launch 3
    projv_qk_kernel<<<3072, 256, QK_SMEM_BYTES>>>(zy, Wv, bv);      // launch 4 (profiled)
    pv_mma<<<dim3(8, 2, 16), 256, PV_SMEM_BYTES>>>();               // launch 5
    reduce4<<<(BB * PP * CC / 4) / 256, 256>>>(out);                // launch 6
}